// round 2
// baseline (speedup 1.0000x reference)
#include <cuda_runtime.h>
#include <cuda_bf16.h>
#include <cstdint>

// DeterministicLattice: ring-stencil fusion + 5-output "GenesisGeometry" engine.
// fused = (phi*x[i] + x[i-1] + x[i+1]) / (phi + 2), ring on axis 0 (row ring).
// out planes: [identity_next, bloom(tanh phi f), crown(sigmoid phi f),
//              triad(sin f * cos phi f), spiral(f * exp(-|f|/phi))]

#define PHI_F      1.6180339887498949f
#define INVPHI_F   0.6180339887498949f
#define INV_PHI2_F 0.2763932022500210f  // 1/(PHI+2)

// DIM = 512 floats/row -> 128 float4 per row (compile-time: shifts, no divide)
#define VPR_LOG2   7
#define VPR        128
#define VPR_MASK   127

__device__ __forceinline__ void genesis_engine(float f,
                                               float& idn, float& bl,
                                               float& cr,  float& tr,
                                               float& sp)
{
    // tanh(f) via one EX2 + one RCP
    float e2 = __expf(f + f);                       // e^{2f}
    float t  = __fdividef(e2 - 1.0f, e2 + 1.0f);    // tanh(f)
    idn = fmaf(INVPHI_F, t, f);                     // identity_next

    // share E = e^{phi f} between bloom (tanh) and crown (sigmoid)
    float E  = __expf(PHI_F * f);
    float E2 = E * E;                               // e^{2 phi f}
    bl = __fdividef(E2 - 1.0f, E2 + 1.0f);          // tanh(phi f)
    cr = __fdividef(E, E + 1.0f);                   // sigmoid(phi f)

    tr = __sinf(f) * __cosf(PHI_F * f);             // triad
    sp = f * __expf(-fabsf(f) * INVPHI_F);          // spiral
}

__device__ __forceinline__ void compute_and_store(float4 s, float4 l, float4 r,
                                                  float4* __restrict__ ov,
                                                  int idx, int total4)
{
    float fs[4] = { s.x, s.y, s.z, s.w };
    float fl[4] = { l.x, l.y, l.z, l.w };
    float fr[4] = { r.x, r.y, r.z, r.w };

    float4 o_idn, o_bl, o_cr, o_tr, o_sp;
    float* pi = &o_idn.x; float* pb = &o_bl.x; float* pc = &o_cr.x;
    float* pt = &o_tr.x;  float* ps = &o_sp.x;

#pragma unroll
    for (int k = 0; k < 4; ++k) {
        float f = (fmaf(PHI_F, fs[k], fl[k]) + fr[k]) * INV_PHI2_F;
        genesis_engine(f, pi[k], pb[k], pc[k], pt[k], ps[k]);
    }

    // Streaming stores: outputs are never re-read; keep them out of L2's way
    // so input ring-reuse lines stay resident.
    __stcs(ov + 0 * total4 + idx, o_idn);
    __stcs(ov + 1 * total4 + idx, o_bl);
    __stcs(ov + 2 * total4 + idx, o_cr);
    __stcs(ov + 3 * total4 + idx, o_tr);
    __stcs(ov + 4 * total4 + idx, o_sp);
}

__global__ void __launch_bounds__(256)
DeterministicLattice_43508018709032_kernel(const float4* __restrict__ xv,
                                           float4* __restrict__ ov,
                                           int nrows)
{
    const int total4 = nrows << VPR_LOG2;
    const int mask   = nrows - 1;                   // nrows is a power of two

    // ILP=2: each block covers 512 consecutive float4s; thread handles
    // idx0 and idx0+256 (coalesced within each half).
    const int idx0 = blockIdx.x * 512 + threadIdx.x;
    const int idx1 = idx0 + 256;

    // ---- element 0 addresses ----
    const int row0 = idx0 >> VPR_LOG2;
    const int col0 = idx0 & VPR_MASK;
    const int l0   = ((row0 - 1) & mask) << VPR_LOG2;
    const int r0   = ((row0 + 1) & mask) << VPR_LOG2;

    // ---- element 1 addresses ----
    const int row1 = idx1 >> VPR_LOG2;
    const int col1 = idx1 & VPR_MASK;
    const int l1   = ((row1 - 1) & mask) << VPR_LOG2;
    const int r1   = ((row1 + 1) & mask) << VPR_LOG2;

    bool ok0 = idx0 < total4;
    bool ok1 = idx1 < total4;

    // Front-batch all 6 loads for maximum MLP
    float4 s0, la0, ra0, s1, la1, ra1;
    if (ok0) { s0 = xv[idx0]; la0 = xv[l0 + col0]; ra0 = xv[r0 + col0]; }
    if (ok1) { s1 = xv[idx1]; la1 = xv[l1 + col1]; ra1 = xv[r1 + col1]; }

    if (ok0) compute_and_store(s0, la0, ra0, ov, idx0, total4);
    if (ok1) compute_and_store(s1, la1, ra1, ov, idx1, total4);
}

extern "C" void kernel_launch(void* const* d_in, const int* in_sizes, int n_in,
                              void* d_out, int out_size)
{
    const float4* x = (const float4*)d_in[0];
    float4* out = (float4*)d_out;

    const int DIM    = 512;
    const int nrows  = in_sizes[0] / DIM;           // 65536
    const int total4 = nrows * (DIM / 4);           // 8,388,608

    const int threads = 256;
    const int per_block = 512;                      // 2 float4 per thread
    const int blocks = (total4 + per_block - 1) / per_block;
    DeterministicLattice_43508018709032_kernel<<<blocks, threads>>>(x, out, nrows);
}

// round 3
// speedup vs baseline: 1.0171x; 1.0171x over previous
#include <cuda_runtime.h>
#include <cuda_bf16.h>
#include <cstdint>

// DeterministicLattice: ring-stencil fusion + 5-output "GenesisGeometry" engine.
// fused f = (phi*x[i] + x[i-1] + x[i+1]) / (phi + 2), ring on axis 0.
// out planes: [f + tanh(f)/phi, tanh(phi f), sigmoid(phi f),
//              sin(f)cos(phi f), f*exp(-|f|/phi)]
//
// MUFU-minimal engine (5 MUFU/elem): work in g=|f|,
//   Ea = e^{phi g}, ca = e^{-g/phi}   (2x EX2)
//   e^g = Ea*ca  (phi - 1/phi = 1), e^{2g} = (Ea*ca)^2   -> no 3rd EX2
//   one batched reciprocal r = 1/((q2+1)(E2+1)(Ea+1)) replaces 3 RCPs
//   sin, cos (2 MUFU)

#define PHI_F      1.6180339887498949f
#define INVPHI_F   0.6180339887498949f
#define INV_PHI2_F 0.2763932022500210f  // 1/(PHI+2)

#define VPR_LOG2   7      // 128 float4 per row (DIM=512)
#define VPR_MASK   127

__device__ __forceinline__ void genesis_engine(float f,
                                               float& idn, float& bl,
                                               float& cr,  float& tr,
                                               float& sp)
{
    const float g   = fabsf(f);
    const float sgn = copysignf(1.0f, f);

    const float Ea = __expf(PHI_F * g);        // e^{phi g}     (EX2)
    const float ca = __expf(-INVPHI_F * g);    // e^{-g/phi}    (EX2)

    const float E2 = Ea * Ea;                  // e^{2 phi g}
    const float eg = Ea * ca;                  // e^{g}
    const float q2 = eg * eg;                  // e^{2g}

    const float A = q2 + 1.0f;
    const float B = E2 + 1.0f;
    const float C = Ea + 1.0f;

    // one RCP for all three denominators
    const float r  = __fdividef(1.0f, A * B * C);   // MUFU.RCP + mul
    const float rA = B * C * r;                     // 1/A
    const float rB = A * C * r;                     // 1/B
    const float rC = A * B * r;                     // 1/C

    const float t = (q2 - 1.0f) * rA * sgn;    // tanh(f)
    bl = (E2 - 1.0f) * rB * sgn;               // tanh(phi f)
    const float s = Ea * rC;                   // sigmoid(phi g)
    cr = (f >= 0.0f) ? s : (1.0f - s);         // sigmoid(phi f)

    idn = fmaf(INVPHI_F, t, f);                // identity_next
    tr  = __sinf(f) * __cosf(PHI_F * f);       // triad    (SIN, COS)
    sp  = f * ca;                              // spiral: f * e^{-|f|/phi}
}

__global__ void __launch_bounds__(256)
DeterministicLattice_43508018709032_kernel(const float4* __restrict__ xv,
                                           float4* __restrict__ ov,
                                           int nrows)
{
    const int total4 = nrows << VPR_LOG2;
    const int idx = blockIdx.x * 256 + threadIdx.x;
    if (idx >= total4) return;

    const int row  = idx >> VPR_LOG2;
    const int col  = idx & VPR_MASK;
    const int mask = nrows - 1;                 // nrows is a power of two
    const int lrow = ((row - 1) & mask) << VPR_LOG2;
    const int rrow = ((row + 1) & mask) << VPR_LOG2;

    const float4 s = xv[idx];
    const float4 l = xv[lrow + col];
    const float4 r = xv[rrow + col];

    const float fs[4] = { s.x, s.y, s.z, s.w };
    const float fl[4] = { l.x, l.y, l.z, l.w };
    const float fr[4] = { r.x, r.y, r.z, r.w };

    float4 o_idn, o_bl, o_cr, o_tr, o_sp;
    float* pi = &o_idn.x; float* pb = &o_bl.x; float* pc = &o_cr.x;
    float* pt = &o_tr.x;  float* ps = &o_sp.x;

#pragma unroll
    for (int k = 0; k < 4; ++k) {
        const float f = (fmaf(PHI_F, fs[k], fl[k]) + fr[k]) * INV_PHI2_F;
        genesis_engine(f, pi[k], pb[k], pc[k], pt[k], ps[k]);
    }

    // Streaming stores: outputs are never re-read.
    __stcs(ov + 0 * total4 + idx, o_idn);
    __stcs(ov + 1 * total4 + idx, o_bl);
    __stcs(ov + 2 * total4 + idx, o_cr);
    __stcs(ov + 3 * total4 + idx, o_tr);
    __stcs(ov + 4 * total4 + idx, o_sp);
}

extern "C" void kernel_launch(void* const* d_in, const int* in_sizes, int n_in,
                              void* d_out, int out_size)
{
    const float4* x = (const float4*)d_in[0];
    float4* out = (float4*)d_out;

    const int DIM    = 512;
    const int nrows  = in_sizes[0] / DIM;       // 65536
    const int total4 = nrows * (DIM / 4);       // 8,388,608

    const int threads = 256;
    const int blocks  = (total4 + threads - 1) / threads;
    DeterministicLattice_43508018709032_kernel<<<blocks, threads>>>(x, out, nrows);
}